// round 9
// baseline (speedup 1.0000x reference)
#include <cuda_runtime.h>

// B=32, P=3, D=300, N=2048.  x,y: [B,P,D,N] fp32.
// out: [B, P*N, 3] = {cos, l2, l1} per (b,p,n) vector of length D (stride N).
//
// float2 per thread (2 consecutive columns): each warp LDG.64 covers exactly
// one 256B-aligned L2 chunk -> one DRAM burst per request, removing the
// split-chunk scatter that capped R5/R8 at 75-78% DRAM. Latency coverage at
// ~32% occ: ~20.7 warps/SM x 9 loads x 256B ~ 47KB in flight > ~25KB needed.

#define D_DIM 300
#define N_DIM 2048
#define N2 (N_DIM / 2)       // 1024 float2 columns per row
#define BP 96
#define THREADS 64

__device__ __forceinline__ float2 ldg2_l2_256(const float2* p)
{
    float2 v;
    asm("ld.global.nc.L2::256B.v2.f32 {%0, %1}, [%2];"
        : "=f"(v.x), "=f"(v.y) : "l"(p));
    return v;
}

__global__ __launch_bounds__(THREADS)
void sim_measure_kernel(const float* __restrict__ x,
                        const float* __restrict__ y,
                        float* __restrict__ out)
{
    const int idx = blockIdx.x * THREADS + threadIdx.x;   // float2-column id
    const int n2 = idx & (N2 - 1);
    const int bp = idx >> 10;                             // / 1024

    const float2* __restrict__ xp =
        reinterpret_cast<const float2*>(x) + (size_t)bp * D_DIM * N2 + n2;
    const float2* __restrict__ yp =
        reinterpret_cast<const float2*>(y) + (size_t)bp * D_DIM * N2 + n2;

    float dot0 = 0.f, xx0 = 0.f, yy0 = 0.f, dd0 = 0.f, l10 = 0.f;
    float dot1 = 0.f, xx1 = 0.f, yy1 = 0.f, dd1 = 0.f, l11 = 0.f;

    #pragma unroll 5
    for (int d = 0; d < D_DIM; ++d) {
        const float2 a = ldg2_l2_256(xp + (size_t)d * N2);
        const float2 b = ldg2_l2_256(yp + (size_t)d * N2);

        dot0 = fmaf(a.x, b.x, dot0);
        xx0  = fmaf(a.x, a.x, xx0);
        yy0  = fmaf(b.x, b.x, yy0);
        const float d0 = a.x - b.x;
        dd0  = fmaf(d0, d0, dd0);
        l10 += fabsf(d0);

        dot1 = fmaf(a.y, b.y, dot1);
        xx1  = fmaf(a.y, a.y, xx1);
        yy1  = fmaf(b.y, b.y, yy1);
        const float d1 = a.y - b.y;
        dd1  = fmaf(d1, d1, dd1);
        l11 += fabsf(d1);
    }

    // out layout: [bp, n, 3], n = n2*2 and n2*2+1
    float* o = out + ((size_t)bp * N_DIM + n2 * 2) * 3;
    o[0] = dot0 * rsqrtf(xx0 * yy0);
    o[1] = sqrtf(dd0);
    o[2] = l10;
    o[3] = dot1 * rsqrtf(xx1 * yy1);
    o[4] = sqrtf(dd1);
    o[5] = l11;
}

extern "C" void kernel_launch(void* const* d_in, const int* in_sizes, int n_in,
                              void* d_out, int out_size)
{
    const float* x = (const float*)d_in[0];
    const float* y = (const float*)d_in[1];
    float* out = (float*)d_out;

    const int total_threads = BP * N2;           // 98304
    const int blocks = total_threads / THREADS;  // 1536
    sim_measure_kernel<<<blocks, THREADS>>>(x, y, out);
}

// round 10
// speedup vs baseline: 1.5620x; 1.5620x over previous
#include <cuda_runtime.h>

// B=32, P=3, D=300, N=2048.  x,y: [B,P,D,N] fp32.
// out: [B, P*N, 3] = {cos, l2, l1} per (b,p,n) vector of length D (stride N).
//
// float4 per thread (warp = 512B burst, 32-thr block = 512B, 1536 blocks)
// + forced ping-pong pipeline (2 buffers x 3 d-rows) so each warp keeps
// ~3KB in flight: 10.4 warps/SM x 3KB ~ 31KB/SM, above the ~25KB
// latency-coverage threshold identified across R1..R9. Long contiguous
// bursts target the ~6.2TB/s pattern ceiling that capped 128B/256B shapes.

#define D_DIM 300
#define CH 3                  // d-rows per chunk
#define NCHUNK (D_DIM / CH)   // 100
#define N_DIM 2048
#define N4 (N_DIM / 4)        // 512
#define BP 96
#define THREADS 32

__device__ __forceinline__ float4 ldg4_nc(const float4* p)
{
    float4 v;
    asm("ld.global.nc.L2::256B.v4.f32 {%0, %1, %2, %3}, [%4];"
        : "=f"(v.x), "=f"(v.y), "=f"(v.z), "=f"(v.w) : "l"(p));
    return v;
}

#define LOAD_CHUNK(A_, B_, base)                                    \
    do {                                                            \
        const size_t _o = (size_t)(base) * N4;                      \
        _Pragma("unroll")                                           \
        for (int _i = 0; _i < CH; ++_i) {                           \
            A_[_i] = ldg4_nc(xp + _o + (size_t)_i * N4);            \
            B_[_i] = ldg4_nc(yp + _o + (size_t)_i * N4);            \
        }                                                           \
    } while (0)

#define COMPUTE_CHUNK(A_, B_)                                       \
    do {                                                            \
        _Pragma("unroll")                                           \
        for (int _i = 0; _i < CH; ++_i) {                           \
            const float _ax[4] = {A_[_i].x, A_[_i].y, A_[_i].z, A_[_i].w}; \
            const float _bx[4] = {B_[_i].x, B_[_i].y, B_[_i].z, B_[_i].w}; \
            _Pragma("unroll")                                       \
            for (int _j = 0; _j < 4; ++_j) {                        \
                const float _a = _ax[_j], _b = _bx[_j];             \
                dot[_j] = fmaf(_a, _b, dot[_j]);                    \
                xx [_j] = fmaf(_a, _a, xx [_j]);                    \
                yy [_j] = fmaf(_b, _b, yy [_j]);                    \
                const float _d = _a - _b;                           \
                dd [_j] = fmaf(_d, _d, dd [_j]);                    \
                l1 [_j] += fabsf(_d);                               \
            }                                                       \
        }                                                           \
    } while (0)

__global__ __launch_bounds__(THREADS)
void sim_measure_kernel(const float* __restrict__ x,
                        const float* __restrict__ y,
                        float* __restrict__ out)
{
    const int idx = blockIdx.x * THREADS + threadIdx.x;   // float4-column id
    const int n4 = idx & (N4 - 1);
    const int bp = idx >> 9;                              // / 512

    const float4* __restrict__ xp =
        reinterpret_cast<const float4*>(x) + (size_t)bp * D_DIM * N4 + n4;
    const float4* __restrict__ yp =
        reinterpret_cast<const float4*>(y) + (size_t)bp * D_DIM * N4 + n4;

    float dot[4] = {0.f, 0.f, 0.f, 0.f};
    float xx [4] = {0.f, 0.f, 0.f, 0.f};
    float yy [4] = {0.f, 0.f, 0.f, 0.f};
    float dd [4] = {0.f, 0.f, 0.f, 0.f};
    float l1 [4] = {0.f, 0.f, 0.f, 0.f};

    float4 a0[CH], b0[CH], a1[CH], b1[CH];

    LOAD_CHUNK(a0, b0, 0 * CH);
    LOAD_CHUNK(a1, b1, 1 * CH);

    #pragma unroll 1
    for (int c = 0; c + 3 < NCHUNK; c += 2) {
        COMPUTE_CHUNK(a0, b0);
        LOAD_CHUNK(a0, b0, (c + 2) * CH);
        COMPUTE_CHUNK(a1, b1);
        LOAD_CHUNK(a1, b1, (c + 3) * CH);
    }
    COMPUTE_CHUNK(a0, b0);   // chunk 98
    COMPUTE_CHUNK(a1, b1);   // chunk 99

    // out layout: [bp, n, 3], 4 consecutive n per thread
    const int n0 = n4 * 4;
    float* o = out + ((size_t)bp * N_DIM + n0) * 3;
    #pragma unroll
    for (int j = 0; j < 4; ++j) {
        o[j * 3 + 0] = dot[j] * rsqrtf(xx[j] * yy[j]);
        o[j * 3 + 1] = sqrtf(dd[j]);
        o[j * 3 + 2] = l1[j];
    }
}

extern "C" void kernel_launch(void* const* d_in, const int* in_sizes, int n_in,
                              void* d_out, int out_size)
{
    const float* x = (const float*)d_in[0];
    const float* y = (const float*)d_in[1];
    float* out = (float*)d_out;

    const int total_threads = BP * N4;           // 49152
    const int blocks = total_threads / THREADS;  // 1536
    sim_measure_kernel<<<blocks, THREADS>>>(x, y, out);
}

// round 11
// speedup vs baseline: 1.5844x; 1.0143x over previous
#include <cuda_runtime.h>

// B=32, P=3, D=300, N=2048.  x,y: [B,P,D,N] fp32.
// out: [B, P*N, 3] = {cos, l2, l1} per (b,p,n) vector of length D (stride N).
//
// R10 champion (float4/thread, 1536x32, forced ping-pong) with pipeline
// deepened CH 3->4: 16 LDG.128 in flight/thread (~85KB/SM), covering the
// queueing-inflated DRAM latency near LTS saturation. regs ~96, still not
// occupancy-binding at 1 warp/block.

#define D_DIM 300
#define CH 4                  // d-rows per chunk
#define NCHUNK (D_DIM / CH)   // 75
#define N_DIM 2048
#define N4 (N_DIM / 4)        // 512
#define BP 96
#define THREADS 32

__device__ __forceinline__ float4 ldg4_nc(const float4* p)
{
    float4 v;
    asm("ld.global.nc.L2::256B.v4.f32 {%0, %1, %2, %3}, [%4];"
        : "=f"(v.x), "=f"(v.y), "=f"(v.z), "=f"(v.w) : "l"(p));
    return v;
}

#define LOAD_CHUNK(A_, B_, base)                                    \
    do {                                                            \
        const size_t _o = (size_t)(base) * N4;                      \
        _Pragma("unroll")                                           \
        for (int _i = 0; _i < CH; ++_i) {                           \
            A_[_i] = ldg4_nc(xp + _o + (size_t)_i * N4);            \
            B_[_i] = ldg4_nc(yp + _o + (size_t)_i * N4);            \
        }                                                           \
    } while (0)

#define COMPUTE_CHUNK(A_, B_)                                       \
    do {                                                            \
        _Pragma("unroll")                                           \
        for (int _i = 0; _i < CH; ++_i) {                           \
            const float _ax[4] = {A_[_i].x, A_[_i].y, A_[_i].z, A_[_i].w}; \
            const float _bx[4] = {B_[_i].x, B_[_i].y, B_[_i].z, B_[_i].w}; \
            _Pragma("unroll")                                       \
            for (int _j = 0; _j < 4; ++_j) {                        \
                const float _a = _ax[_j], _b = _bx[_j];             \
                dot[_j] = fmaf(_a, _b, dot[_j]);                    \
                xx [_j] = fmaf(_a, _a, xx [_j]);                    \
                yy [_j] = fmaf(_b, _b, yy [_j]);                    \
                const float _d = _a - _b;                           \
                dd [_j] = fmaf(_d, _d, dd [_j]);                    \
                l1 [_j] += fabsf(_d);                               \
            }                                                       \
        }                                                           \
    } while (0)

__global__ __launch_bounds__(THREADS)
void sim_measure_kernel(const float* __restrict__ x,
                        const float* __restrict__ y,
                        float* __restrict__ out)
{
    const int idx = blockIdx.x * THREADS + threadIdx.x;   // float4-column id
    const int n4 = idx & (N4 - 1);
    const int bp = idx >> 9;                              // / 512

    const float4* __restrict__ xp =
        reinterpret_cast<const float4*>(x) + (size_t)bp * D_DIM * N4 + n4;
    const float4* __restrict__ yp =
        reinterpret_cast<const float4*>(y) + (size_t)bp * D_DIM * N4 + n4;

    float dot[4] = {0.f, 0.f, 0.f, 0.f};
    float xx [4] = {0.f, 0.f, 0.f, 0.f};
    float yy [4] = {0.f, 0.f, 0.f, 0.f};
    float dd [4] = {0.f, 0.f, 0.f, 0.f};
    float l1 [4] = {0.f, 0.f, 0.f, 0.f};

    float4 a0[CH], b0[CH], a1[CH], b1[CH];

    LOAD_CHUNK(a0, b0, 0 * CH);
    LOAD_CHUNK(a1, b1, 1 * CH);

    // NCHUNK = 75: loop (c = 0,2,..,70) computes chunks 0..71 and loads
    // 2..73; epilogue computes 72,73 and loads+computes 74.
    #pragma unroll 1
    for (int c = 0; c + 3 < NCHUNK; c += 2) {
        COMPUTE_CHUNK(a0, b0);
        LOAD_CHUNK(a0, b0, (c + 2) * CH);
        COMPUTE_CHUNK(a1, b1);
        LOAD_CHUNK(a1, b1, (c + 3) * CH);
    }
    COMPUTE_CHUNK(a0, b0);                    // chunk 72
    LOAD_CHUNK(a0, b0, (NCHUNK - 1) * CH);    // chunk 74
    COMPUTE_CHUNK(a1, b1);                    // chunk 73
    COMPUTE_CHUNK(a0, b0);                    // chunk 74

    // out layout: [bp, n, 3], 4 consecutive n per thread
    const int n0 = n4 * 4;
    float* o = out + ((size_t)bp * N_DIM + n0) * 3;
    #pragma unroll
    for (int j = 0; j < 4; ++j) {
        o[j * 3 + 0] = dot[j] * rsqrtf(xx[j] * yy[j]);
        o[j * 3 + 1] = sqrtf(dd[j]);
        o[j * 3 + 2] = l1[j];
    }
}

extern "C" void kernel_launch(void* const* d_in, const int* in_sizes, int n_in,
                              void* d_out, int out_size)
{
    const float* x = (const float*)d_in[0];
    const float* y = (const float*)d_in[1];
    float* out = (float*)d_out;

    const int total_threads = BP * N4;           // 49152
    const int blocks = total_threads / THREADS;  // 1536
    sim_measure_kernel<<<blocks, THREADS>>>(x, y, out);
}

// round 12
// speedup vs baseline: 1.6318x; 1.0299x over previous
#include <cuda_runtime.h>

// B=32, P=3, D=300, N=2048.  x,y: [B,P,D,N] fp32.
// out: [B, P*N, 3] = {cos, l2, l1} per (b,p,n) vector of length D (stride N).
//
// R11 champion (float4/thread, 1536x32, forced ping-pong) deepened CH 4->6:
// 24 LDG.128 in flight/thread (~125KB/SM, under M_max=55/warp). regs ~128,
// harmless at 1 warp/block (RF allows 255). Third notch on the proven
// in-flight-depth axis (R10: 80.2% DRAM, R11: 82.0%).

#define D_DIM 300
#define CH 6                  // d-rows per chunk
#define NCHUNK (D_DIM / CH)   // 50
#define N_DIM 2048
#define N4 (N_DIM / 4)        // 512
#define BP 96
#define THREADS 32

__device__ __forceinline__ float4 ldg4_nc(const float4* p)
{
    float4 v;
    asm("ld.global.nc.L2::256B.v4.f32 {%0, %1, %2, %3}, [%4];"
        : "=f"(v.x), "=f"(v.y), "=f"(v.z), "=f"(v.w) : "l"(p));
    return v;
}

#define LOAD_CHUNK(A_, B_, base)                                    \
    do {                                                            \
        const size_t _o = (size_t)(base) * N4;                      \
        _Pragma("unroll")                                           \
        for (int _i = 0; _i < CH; ++_i) {                           \
            A_[_i] = ldg4_nc(xp + _o + (size_t)_i * N4);            \
            B_[_i] = ldg4_nc(yp + _o + (size_t)_i * N4);            \
        }                                                           \
    } while (0)

#define COMPUTE_CHUNK(A_, B_)                                       \
    do {                                                            \
        _Pragma("unroll")                                           \
        for (int _i = 0; _i < CH; ++_i) {                           \
            const float _ax[4] = {A_[_i].x, A_[_i].y, A_[_i].z, A_[_i].w}; \
            const float _bx[4] = {B_[_i].x, B_[_i].y, B_[_i].z, B_[_i].w}; \
            _Pragma("unroll")                                       \
            for (int _j = 0; _j < 4; ++_j) {                        \
                const float _a = _ax[_j], _b = _bx[_j];             \
                dot[_j] = fmaf(_a, _b, dot[_j]);                    \
                xx [_j] = fmaf(_a, _a, xx [_j]);                    \
                yy [_j] = fmaf(_b, _b, yy [_j]);                    \
                const float _d = _a - _b;                           \
                dd [_j] = fmaf(_d, _d, dd [_j]);                    \
                l1 [_j] += fabsf(_d);                               \
            }                                                       \
        }                                                           \
    } while (0)

__global__ __launch_bounds__(THREADS)
void sim_measure_kernel(const float* __restrict__ x,
                        const float* __restrict__ y,
                        float* __restrict__ out)
{
    const int idx = blockIdx.x * THREADS + threadIdx.x;   // float4-column id
    const int n4 = idx & (N4 - 1);
    const int bp = idx >> 9;                              // / 512

    const float4* __restrict__ xp =
        reinterpret_cast<const float4*>(x) + (size_t)bp * D_DIM * N4 + n4;
    const float4* __restrict__ yp =
        reinterpret_cast<const float4*>(y) + (size_t)bp * D_DIM * N4 + n4;

    float dot[4] = {0.f, 0.f, 0.f, 0.f};
    float xx [4] = {0.f, 0.f, 0.f, 0.f};
    float yy [4] = {0.f, 0.f, 0.f, 0.f};
    float dd [4] = {0.f, 0.f, 0.f, 0.f};
    float l1 [4] = {0.f, 0.f, 0.f, 0.f};

    float4 a0[CH], b0[CH], a1[CH], b1[CH];

    LOAD_CHUNK(a0, b0, 0 * CH);
    LOAD_CHUNK(a1, b1, 1 * CH);

    // NCHUNK = 50 (even): loop (c = 0,2,..,46) computes chunks 0..47 and
    // loads 2..49; epilogue computes the pre-loaded 48, 49.
    #pragma unroll 1
    for (int c = 0; c + 3 < NCHUNK; c += 2) {
        COMPUTE_CHUNK(a0, b0);
        LOAD_CHUNK(a0, b0, (c + 2) * CH);
        COMPUTE_CHUNK(a1, b1);
        LOAD_CHUNK(a1, b1, (c + 3) * CH);
    }
    COMPUTE_CHUNK(a0, b0);   // chunk 48
    COMPUTE_CHUNK(a1, b1);   // chunk 49

    // out layout: [bp, n, 3], 4 consecutive n per thread
    const int n0 = n4 * 4;
    float* o = out + ((size_t)bp * N_DIM + n0) * 3;
    #pragma unroll
    for (int j = 0; j < 4; ++j) {
        o[j * 3 + 0] = dot[j] * rsqrtf(xx[j] * yy[j]);
        o[j * 3 + 1] = sqrtf(dd[j]);
        o[j * 3 + 2] = l1[j];
    }
}

extern "C" void kernel_launch(void* const* d_in, const int* in_sizes, int n_in,
                              void* d_out, int out_size)
{
    const float* x = (const float*)d_in[0];
    const float* y = (const float*)d_in[1];
    float* out = (float*)d_out;

    const int total_threads = BP * N4;           // 49152
    const int blocks = total_threads / THREADS;  // 1536
    sim_measure_kernel<<<blocks, THREADS>>>(x, y, out);
}